// round 3
// baseline (speedup 1.0000x reference)
#include <cuda_runtime.h>
#include <cuda_bf16.h>

// FlowBasedDensityPotential: energy = 0.5 * sum(|grad phi|^2) with central
// differences (one-sided at boundaries) on a 2048x2048 f32 grid.
// 'pos' input is dead (never affects the output) and is ignored.
//
// R2: front-batched loads — each thread issues ALL 14 loads (6 float4 rows +
// 8 halo scalars) before any compute, raising per-thread MLP from ~2 to ~14
// to cover DRAM/L2 latency (R1 showed 19.7% DRAM, 38% issue: latency-bound).

#define NX 2048
#define NY 2048
#define RPT 4                         // rows per thread
#define BLOCK 256
#define CHUNKS_PER_BAND (NY / 4)      // 512 float4 chunks per row band
#define NUM_BANDS (NX / RPT)          // 512
#define TOTAL_THREADS (CHUNKS_PER_BAND * NUM_BANDS)   // 262144
#define NUM_BLOCKS (TOTAL_THREADS / BLOCK)            // 1024

__device__ double       g_partials[NUM_BLOCKS];
__device__ unsigned int g_ticket = 0;

__global__ void __launch_bounds__(BLOCK)
flow_energy_kernel(const float* __restrict__ phi, float* __restrict__ out)
{
    const int t    = blockIdx.x * BLOCK + threadIdx.x;
    const int jc   = t & (CHUNKS_PER_BAND - 1);   // chunk index along y (lane-contiguous)
    const int band = t >> 9;                      // row band index
    const int j0   = jc * 4;
    const int i0   = band * RPT;

    const float C1 = 1024.0f;   // 1/(2h), h = 1/2048
    const float C2 = 2048.0f;   // 1/h (one-sided boundary)

    // ---- FRONT-BATCHED LOADS: issue everything before any compute ----
    // Rows i0-1 .. i0+4, row index clamped to [0, NX-1] (clamped values are
    // never used by the one-sided boundary formulas below).
    float4 a[RPT + 2];
    #pragma unroll
    for (int k = 0; k < RPT + 2; ++k) {
        int ri = i0 - 1 + k;
        ri = ri < 0 ? 0 : (ri > NX - 1 ? NX - 1 : ri);
        a[k] = *reinterpret_cast<const float4*>(phi + (size_t)ri * NY + j0);
    }
    // Halo scalars for each computed row; column clamped (unused at y-edges).
    const int jl = j0 > 0 ? j0 - 1 : 0;
    const int jr = j0 + 4 < NY ? j0 + 4 : NY - 1;
    float hl[RPT], hr[RPT];
    #pragma unroll
    for (int r = 0; r < RPT; ++r) {
        const size_t row = (size_t)(i0 + r) * NY;
        hl[r] = phi[row + jl];
        hr[r] = phi[row + jr];
    }

    // ---- COMPUTE ----
    float acc = 0.0f;
    #pragma unroll
    for (int r = 0; r < RPT; ++r) {
        const int i = i0 + r;
        const float4 prev = a[r];
        const float4 cur  = a[r + 1];
        const float4 next = a[r + 2];

        float4 dx;
        if (i == 0) {
            dx.x = (next.x - cur.x) * C2;
            dx.y = (next.y - cur.y) * C2;
            dx.z = (next.z - cur.z) * C2;
            dx.w = (next.w - cur.w) * C2;
        } else if (i == NX - 1) {
            dx.x = (cur.x - prev.x) * C2;
            dx.y = (cur.y - prev.y) * C2;
            dx.z = (cur.z - prev.z) * C2;
            dx.w = (cur.w - prev.w) * C2;
        } else {
            dx.x = (next.x - prev.x) * C1;
            dx.y = (next.y - prev.y) * C1;
            dx.z = (next.z - prev.z) * C1;
            dx.w = (next.w - prev.w) * C1;
        }

        float dy0 = (j0 == 0)      ? (cur.y - cur.x) * C2 : (cur.y - hl[r]) * C1;
        float dy1 = (cur.z - cur.x) * C1;
        float dy2 = (cur.w - cur.y) * C1;
        float dy3 = (j0 + 4 == NY) ? (cur.w - cur.z) * C2 : (hr[r] - cur.z) * C1;

        acc += dx.x * dx.x + dy0 * dy0;
        acc += dx.y * dx.y + dy1 * dy1;
        acc += dx.z * dx.z + dy2 * dy2;
        acc += dx.w * dx.w + dy3 * dy3;
    }

    // ---- block reduction (float tree; <= 16 terms/thread) ----
    #pragma unroll
    for (int off = 16; off; off >>= 1)
        acc += __shfl_xor_sync(0xffffffffu, acc, off);

    __shared__ float  s_warp[BLOCK / 32];
    __shared__ bool   s_is_last;
    if ((threadIdx.x & 31) == 0)
        s_warp[threadIdx.x >> 5] = acc;
    __syncthreads();

    if (threadIdx.x < 32) {
        float v = (threadIdx.x < BLOCK / 32) ? s_warp[threadIdx.x] : 0.0f;
        #pragma unroll
        for (int off = 4; off; off >>= 1)
            v += __shfl_xor_sync(0xffffffffu, v, off);
        if (threadIdx.x == 0) {
            g_partials[blockIdx.x] = (double)v;
            __threadfence();
            unsigned int tk = atomicAdd(&g_ticket, 1u);
            s_is_last = (tk == (unsigned int)(gridDim.x - 1));
        }
    }
    __syncthreads();

    // ---- last block: sum the 1024 double partials, write scalar, reset ticket ----
    if (s_is_last) {
        double d = 0.0;
        for (int k = threadIdx.x; k < NUM_BLOCKS; k += BLOCK)
            d += g_partials[k];
        #pragma unroll
        for (int off = 16; off; off >>= 1)
            d += __shfl_xor_sync(0xffffffffu, d, off);

        __shared__ double s_dwarp[BLOCK / 32];
        if ((threadIdx.x & 31) == 0)
            s_dwarp[threadIdx.x >> 5] = d;
        __syncthreads();
        if (threadIdx.x < 32) {
            double v = (threadIdx.x < BLOCK / 32) ? s_dwarp[threadIdx.x] : 0.0;
            #pragma unroll
            for (int off = 4; off; off >>= 1)
                v += __shfl_xor_sync(0xffffffffu, v, off);
            if (threadIdx.x == 0) {
                out[0] = (float)(0.5 * v);
                g_ticket = 0;   // reset for next (graph-replayed) launch
            }
        }
    }
}

extern "C" void kernel_launch(void* const* d_in, const int* in_sizes, int n_in,
                              void* d_out, int out_size)
{
    // Select phi by element count (2048*2048); 'pos' (2,000,000 elems) is unused.
    const float* phi = nullptr;
    for (int i = 0; i < n_in; ++i) {
        if (in_sizes[i] == NX * NY) { phi = (const float*)d_in[i]; break; }
    }
    if (!phi) phi = (const float*)d_in[n_in - 1];

    flow_energy_kernel<<<NUM_BLOCKS, BLOCK>>>(phi, (float*)d_out);
}